// round 16
// baseline (speedup 1.0000x reference)
#include <cuda_runtime.h>
#include <cuda_bf16.h>
#include <math.h>

#define BB   512   // batch
#define TT   128   // time steps
#define FF   256   // features
#define HH   512   // hidden
#define KK   3     // fuzzy rules

typedef unsigned long long ull;
typedef unsigned int uint;

// ------------------------------------------------------------------
// Device scratch
// ------------------------------------------------------------------
__device__ float g_xw[(size_t)TT * BB * HH];          // [T][B][H]
__device__ __nv_bfloat16 g_hh[2][(size_t)BB * HH];    // h hi, ping-pong [B][H]
__device__ __nv_bfloat16 g_hl[2][(size_t)BB * HH];    // h lo
__device__ __nv_bfloat16 g_Whh[HH * HH];              // Wh hi  [k][n]
__device__ __nv_bfloat16 g_Whl[HH * HH];              // Wh lo
__device__ __nv_bfloat16 g_Wxh[FF * HH];              // (sigmoid(theta)*Wx) hi
__device__ __nv_bfloat16 g_Wxl[FF * HH];              // (sigmoid(theta)*Wx) lo
__device__ __nv_bfloat16 g_xh[(size_t)BB * TT * FF];  // x hi  [b*T+t][f]
__device__ __nv_bfloat16 g_xl[(size_t)BB * TT * FF];  // x lo
__device__ float g_gp[(HH / 2) * 20];                 // packed gate params / col-pair

// ------------------------------------------------------------------
// Helpers
// ------------------------------------------------------------------
__device__ __forceinline__ uint smem_u32(const void* p) {
    return (uint)__cvta_generic_to_shared(p);
}
__device__ __forceinline__ void ldmx4(uint* r, uint addr) {
    asm volatile("ldmatrix.sync.aligned.m8n8.x4.shared.b16 {%0,%1,%2,%3}, [%4];"
                 : "=r"(r[0]), "=r"(r[1]), "=r"(r[2]), "=r"(r[3]) : "r"(addr));
}
__device__ __forceinline__ void ldmx4t(uint* r, uint addr) {
    asm volatile("ldmatrix.sync.aligned.m8n8.x4.trans.shared.b16 {%0,%1,%2,%3}, [%4];"
                 : "=r"(r[0]), "=r"(r[1]), "=r"(r[2]), "=r"(r[3]) : "r"(addr));
}
__device__ __forceinline__ void mma16816(float* d, const uint* a, uint b0, uint b1) {
    asm volatile("mma.sync.aligned.m16n8k16.row.col.f32.bf16.bf16.f32 "
                 "{%0,%1,%2,%3}, {%4,%5,%6,%7}, {%8,%9}, {%0,%1,%2,%3};"
                 : "+f"(d[0]), "+f"(d[1]), "+f"(d[2]), "+f"(d[3])
                 : "r"(a[0]), "r"(a[1]), "r"(a[2]), "r"(a[3]), "r"(b0), "r"(b1));
}
__device__ __forceinline__ void cpasync16(uint saddr, const void* gaddr) {
    asm volatile("cp.async.cg.shared.global [%0], [%1], 16;"
                 :: "r"(saddr), "l"(gaddr));
}

// ------------------------------------------------------------------
// Prep: zero h0, split Wh and Wxs into bf16 hi/lo, emit weights, gate params.
// ------------------------------------------------------------------
__global__ void prep_kernel(const float* __restrict__ theta,
                            const float* __restrict__ Wx,
                            const float* __restrict__ Wh,
                            const float* __restrict__ sigma,
                            const float* __restrict__ cC,
                            const float* __restrict__ qQ,
                            const float* __restrict__ bias,
                            float* __restrict__ out)
{
    int idx = blockIdx.x * blockDim.x + threadIdx.x;   // 262144 threads
    if (idx < BB * HH) {
        g_hh[0][idx] = __float2bfloat16_rn(0.0f);
        g_hl[0][idx] = __float2bfloat16_rn(0.0f);
    }
    if (idx < HH * HH) {
        float w = Wh[idx];
        __nv_bfloat16 hi = __float2bfloat16_rn(w);
        g_Whh[idx] = hi;
        g_Whl[idx] = __float2bfloat16_rn(w - __bfloat162float(hi));
    }
    if (idx < FF * HH) {
        int f = idx >> 9;
        float w = (1.0f / (1.0f + expf(-theta[f]))) * Wx[idx];
        __nv_bfloat16 hi = __float2bfloat16_rn(w);
        g_Wxh[idx] = hi;
        g_Wxl[idx] = __float2bfloat16_rn(w - __bfloat162float(hi));
    }
    if (idx < FF) out[BB + idx] = 1.0f / (1.0f + expf(-theta[idx]));
    if (idx < HH / 2) {
        float* gp = g_gp + idx * 20;
        #pragma unroll
        for (int j = 0; j < 2; ++j) {
            int col = idx * 2 + j;
            float* o = gp + j * 10;
            #pragma unroll
            for (int s = 0; s < 3; ++s) {
                float sg = sigma[col * 3 + s];
                o[0 + s] = cC[col * 3 + s];
                o[4 + s] = 1.0f / (2.0f * sg * sg + 1e-8f);
                o[7 + s] = qQ[col * 3 + s];
            }
            o[3] = bias[col];
        }
    }
}

// ------------------------------------------------------------------
// x -> bf16 hi/lo split.
// ------------------------------------------------------------------
__global__ void __launch_bounds__(256) xcvt_kernel(const float* __restrict__ x)
{
    size_t i = ((size_t)blockIdx.x * 256 + threadIdx.x) * 4;
    float4 v = *(const float4*)(x + i);
    __nv_bfloat16 h0 = __float2bfloat16_rn(v.x);
    __nv_bfloat16 h1 = __float2bfloat16_rn(v.y);
    __nv_bfloat16 h2 = __float2bfloat16_rn(v.z);
    __nv_bfloat16 h3 = __float2bfloat16_rn(v.w);
    __nv_bfloat162 hv0; hv0.x = h0; hv0.y = h1;
    __nv_bfloat162 hv1; hv1.x = h2; hv1.y = h3;
    __nv_bfloat162 lv0;
    lv0.x = __float2bfloat16_rn(v.x - __bfloat162float(h0));
    lv0.y = __float2bfloat16_rn(v.y - __bfloat162float(h1));
    __nv_bfloat162 lv1;
    lv1.x = __float2bfloat16_rn(v.z - __bfloat162float(h2));
    lv1.y = __float2bfloat16_rn(v.w - __bfloat162float(h3));
    *(__nv_bfloat162*)(g_xh + i)     = hv0;
    *(__nv_bfloat162*)(g_xh + i + 2) = hv1;
    *(__nv_bfloat162*)(g_xl + i)     = lv0;
    *(__nv_bfloat162*)(g_xl + i + 2) = lv1;
}

// ------------------------------------------------------------------
// GEMM1 (HMMA hi/lo, proven): g_xw[t][b][h] = sum_f x[m][f] * Wxs[f][h]
// ------------------------------------------------------------------
#define SA1_PITCH 264
#define SB1_PITCH 136
#define SM1_AH 0
#define SM1_AL (64 * SA1_PITCH * 2)
#define SM1_BH (2 * 64 * SA1_PITCH * 2)
#define SM1_BL (SM1_BH + FF * SB1_PITCH * 2)
#define SMEM_G1_BYTES (SM1_BL + FF * SB1_PITCH * 2)

__global__ void __launch_bounds__(256, 1) gemm1_hmma()
{
    extern __shared__ char smem[];
    __nv_bfloat16* sAh = (__nv_bfloat16*)(smem + SM1_AH);
    __nv_bfloat16* sAl = (__nv_bfloat16*)(smem + SM1_AL);
    __nv_bfloat16* sBh = (__nv_bfloat16*)(smem + SM1_BH);
    __nv_bfloat16* sBl = (__nv_bfloat16*)(smem + SM1_BL);

    const int tid = threadIdx.x;
    const int m0  = blockIdx.x * 64;
    const int n0  = blockIdx.y * 128;

    {
        #pragma unroll
        for (int j = 0; j < 8; ++j) {
            int flat = tid + 256 * j;
            int row  = flat >> 5;
            int c8   = flat & 31;
            const size_t src = (size_t)(m0 + row) * FF + c8 * 8;
            *(uint4*)(sAh + row * SA1_PITCH + c8 * 8) = *(const uint4*)(g_xh + src);
            *(uint4*)(sAl + row * SA1_PITCH + c8 * 8) = *(const uint4*)(g_xl + src);
        }
    }
    {
        #pragma unroll
        for (int j = 0; j < 16; ++j) {
            int flat = tid + 256 * j;
            int row  = flat >> 4;
            int c8   = flat & 15;
            const size_t src = (size_t)row * HH + n0 + c8 * 8;
            *(uint4*)(sBh + row * SB1_PITCH + c8 * 8) = *(const uint4*)(g_Wxh + src);
            *(uint4*)(sBl + row * SB1_PITCH + c8 * 8) = *(const uint4*)(g_Wxl + src);
        }
    }
    __syncthreads();

    const int warp = tid >> 5;
    const int lane = tid & 31;
    const int mw   = warp & 1;
    const int nw   = warp >> 1;

    uint aAddrH[2], aAddrL[2];
    #pragma unroll
    for (int a = 0; a < 2; ++a) {
        int aRow = mw * 32 + a * 16 + (lane & 15);
        int aCol = (lane >> 4) * 8;
        aAddrH[a] = smem_u32(sAh + aRow * SA1_PITCH + aCol);
        aAddrL[a] = aAddrH[a] + (SM1_AL - SM1_AH);
    }
    uint bAddrH[2], bAddrL[2];
    #pragma unroll
    for (int bsub = 0; bsub < 2; ++bsub) {
        int bRow = lane & 15;
        int bCol = nw * 32 + bsub * 16 + (lane >> 4) * 8;
        bAddrH[bsub] = smem_u32(sBh + bRow * SB1_PITCH + bCol);
        bAddrL[bsub] = bAddrH[bsub] + (SM1_BL - SM1_BH);
    }

    float acc[2][4][4];
    #pragma unroll
    for (int a = 0; a < 2; ++a)
        #pragma unroll
        for (int j = 0; j < 4; ++j)
            #pragma unroll
            for (int r = 0; r < 4; ++r) acc[a][j][r] = 0.f;

    #pragma unroll 2
    for (int ks = 0; ks < 16; ++ks) {
        uint ah[2][4], al[2][4], bh[2][4], bl[2][4];
        #pragma unroll
        for (int a = 0; a < 2; ++a) {
            ldmx4(ah[a], aAddrH[a] + ks * 32);
            ldmx4(al[a], aAddrL[a] + ks * 32);
        }
        #pragma unroll
        for (int bsub = 0; bsub < 2; ++bsub) {
            ldmx4t(bh[bsub], bAddrH[bsub] + ks * (16 * SB1_PITCH * 2));
            ldmx4t(bl[bsub], bAddrL[bsub] + ks * (16 * SB1_PITCH * 2));
        }
        #pragma unroll
        for (int a = 0; a < 2; ++a) {
            #pragma unroll
            for (int bsub = 0; bsub < 2; ++bsub) {
                float* d0 = acc[a][bsub * 2 + 0];
                float* d1 = acc[a][bsub * 2 + 1];
                mma16816(d0, ah[a], bh[bsub][0], bh[bsub][1]);
                mma16816(d0, ah[a], bl[bsub][0], bl[bsub][1]);
                mma16816(d0, al[a], bh[bsub][0], bh[bsub][1]);
                mma16816(d1, ah[a], bh[bsub][2], bh[bsub][3]);
                mma16816(d1, ah[a], bl[bsub][2], bl[bsub][3]);
                mma16816(d1, al[a], bh[bsub][2], bh[bsub][3]);
            }
        }
    }

    #pragma unroll
    for (int a = 0; a < 2; ++a) {
        #pragma unroll
        for (int j = 0; j < 4; ++j) {
            const int col = n0 + nw * 32 + j * 8 + (lane & 3) * 2;
            #pragma unroll
            for (int p = 0; p < 2; ++p) {
                int rl = mw * 32 + a * 16 + (lane >> 2) + p * 8;
                int m  = m0 + rl;
                int t  = m & (TT - 1);
                int b  = m >> 7;
                float2 v = make_float2(acc[a][j][2 * p], acc[a][j][2 * p + 1]);
                *(float2*)&g_xw[((size_t)t * BB + b) * HH + col] = v;
            }
        }
    }
}

// ------------------------------------------------------------------
// Step kernel v12: R14 base (256 thr) + 3 independent acc chains +
// software-pipelined ldmatrix + PDL trigger moved AFTER epilogue
// (race-free: all h stores precede the trigger).
// ------------------------------------------------------------------
#define SA_PITCH 520
#define SB_PITCH 72
#define SMEM_AH  0
#define SMEM_AL  (32 * SA_PITCH * 2)
#define SMEM_BH  (2 * 32 * SA_PITCH * 2)
#define SMEM_BL  (SMEM_BH + HH * SB_PITCH * 2)
#define SMEM_STEP_BYTES (SMEM_BL + HH * SB_PITCH * 2)

__global__ void __launch_bounds__(256, 1) step_kernel(int t)
{
    extern __shared__ char smem[];
    __nv_bfloat16* sAh = (__nv_bfloat16*)(smem + SMEM_AH);
    __nv_bfloat16* sAl = (__nv_bfloat16*)(smem + SMEM_AL);

    const int tid = threadIdx.x;
    const int m0  = blockIdx.x * 32;
    const int n0  = blockIdx.y * 64;

    const uint sAhU = smem_u32(smem + SMEM_AH);
    const uint sAlU = smem_u32(smem + SMEM_AL);
    const uint sBhU = smem_u32(smem + SMEM_BH);
    const uint sBlU = smem_u32(smem + SMEM_BL);

    // ---- stage B (Wh hi/lo slice) — independent of predecessor ----
    {
        #pragma unroll
        for (int j = 0; j < 16; ++j) {
            int flat = tid + 256 * j;          // < 4096
            int row  = flat >> 3;              // 0..511
            int c8   = flat & 7;
            const size_t src = (size_t)row * HH + n0 + c8 * 8;
            cpasync16(sBhU + (row * SB_PITCH + c8 * 8) * 2, g_Whh + src);
            cpasync16(sBlU + (row * SB_PITCH + c8 * 8) * 2, g_Whl + src);
        }
    }
    asm volatile("cp.async.commit_group;" ::: "memory");

    const int warp = tid >> 5;
    const int lane = tid & 31;
    const int mw   = warp & 1;
    const int nw   = warp >> 1;
    const int rl0  = mw * 16 + (lane >> 2);
    const int c0   = (lane & 3) * 2;

    // ---- gate params (prep output, 2+ kernels back — safe pre-sync) ----
    float4 gpre[2][5];
    #pragma unroll
    for (int half = 0; half < 2; ++half) {
        const int colg = n0 + nw * 16 + half * 8 + c0;
        const float* gp = g_gp + (size_t)(colg >> 1) * 20;
        gpre[half][0] = *(const float4*)(gp + 0);
        gpre[half][1] = *(const float4*)(gp + 4);
        gpre[half][2] = *(const float4*)(gp + 8);
        gpre[half][3] = *(const float4*)(gp + 12);
        gpre[half][4] = *(const float4*)(gp + 16);
    }

    // ---- wait for predecessor's h / xw writes ----
    cudaGridDependencySynchronize();

    const __nv_bfloat16* hh = g_hh[t & 1];
    const __nv_bfloat16* hl = g_hl[t & 1];

    // ---- stage A (h hi/lo) via cp.async ----
    {
        #pragma unroll
        for (int j = 0; j < 8; ++j) {
            int flat = tid + 256 * j;          // < 2048
            int row  = flat >> 6;              // 0..31
            int c8   = flat & 63;
            const size_t src = (size_t)(m0 + row) * HH + c8 * 8;
            cpasync16(sAhU + (row * SA_PITCH + c8 * 8) * 2, hh + src);
            cpasync16(sAlU + (row * SA_PITCH + c8 * 8) * 2, hl + src);
        }
    }
    asm volatile("cp.async.commit_group;" ::: "memory");

    // ---- xw prefetch (DRAM-cold) overlaps the A staging wait ----
    const float* xwt = g_xw + (size_t)t * (BB * HH);
    float2 xpre[2][2];
    #pragma unroll
    for (int half = 0; half < 2; ++half) {
        const int colg = n0 + nw * 16 + half * 8 + c0;
        #pragma unroll
        for (int p = 0; p < 2; ++p) {
            const int rg = m0 + rl0 + p * 8;
            xpre[half][p] = *(const float2*)&xwt[(size_t)rg * HH + colg];
        }
    }

    asm volatile("cp.async.wait_group 0;" ::: "memory");
    __syncthreads();

    // ---- HMMA mainloop: pipelined fragments, 3 independent acc chains ----
    const int aRow = mw * 16 + (lane & 15);
    const int aCol = (lane >> 4) * 8;
    uint aAddrH = sAhU + (aRow * SA_PITCH + aCol) * 2;
    uint aAddrL = aAddrH + (SMEM_AL - SMEM_AH);

    const int bRow = lane & 15;
    const int bCol = nw * 16 + (lane >> 4) * 8;
    uint bAddrH = sBhU + (bRow * SB_PITCH + bCol) * 2;
    uint bAddrL = bAddrH + (SMEM_BL - SMEM_BH);

    float aHH0[4] = {0,0,0,0}, aHL0[4] = {0,0,0,0}, aLH0[4] = {0,0,0,0};
    float aHH1[4] = {0,0,0,0}, aHL1[4] = {0,0,0,0}, aLH1[4] = {0,0,0,0};

    uint ah[2][4], al[2][4], bh[2][4], bl[2][4];
    ldmx4 (ah[0], aAddrH);
    ldmx4 (al[0], aAddrL);
    ldmx4t(bh[0], bAddrH);
    ldmx4t(bl[0], bAddrL);

    #pragma unroll 4
    for (int ks = 0; ks < 32; ++ks) {
        const int cur = ks & 1;
        const int nxt = cur ^ 1;
        if (ks < 31) {
            ldmx4 (ah[nxt], aAddrH + (ks + 1) * 32);
            ldmx4 (al[nxt], aAddrL + (ks + 1) * 32);
            ldmx4t(bh[nxt], bAddrH + (ks + 1) * (16 * SB_PITCH * 2));
            ldmx4t(bl[nxt], bAddrL + (ks + 1) * (16 * SB_PITCH * 2));
        }
        mma16816(aHH0, ah[cur], bh[cur][0], bh[cur][1]);
        mma16816(aHL0, ah[cur], bl[cur][0], bl[cur][1]);
        mma16816(aLH0, al[cur], bh[cur][0], bh[cur][1]);
        mma16816(aHH1, ah[cur], bh[cur][2], bh[cur][3]);
        mma16816(aHL1, ah[cur], bl[cur][2], bl[cur][3]);
        mma16816(aLH1, al[cur], bh[cur][2], bh[cur][3]);
    }

    float acc0[4], acc1[4];
    #pragma unroll
    for (int r = 0; r < 4; ++r) {
        acc0[r] = aHH0[r] + aHL0[r] + aLH0[r];
        acc1[r] = aHH1[r] + aHL1[r] + aLH1[r];
    }

    // ---- fused gate epilogue ----
    __nv_bfloat16* hhn = g_hh[(t + 1) & 1];
    __nv_bfloat16* hln = g_hl[(t + 1) & 1];

    float* accs[2] = {acc0, acc1};
    #pragma unroll
    for (int half = 0; half < 2; ++half) {
        const float* d = accs[half];
        const int colg = n0 + nw * 16 + half * 8 + c0;

        float4 p0 = gpre[half][0];
        float4 p1 = gpre[half][1];
        float4 p2 = gpre[half][2];
        float4 p3 = gpre[half][3];
        float4 p4 = gpre[half][4];
        float cc[2][3]  = {{p0.x, p0.y, p0.z}, {p2.z, p2.w, p3.x}};
        float bb2[2]    = {p0.w, p3.y};
        float iv[2][3]  = {{p1.x, p1.y, p1.z}, {p3.z, p3.w, p4.x}};
        float qq[2][3]  = {{p1.w, p2.x, p2.y}, {p4.y, p4.z, p4.w}};

        #pragma unroll
        for (int p = 0; p < 2; ++p) {
            const int rl = rl0 + p * 8;
            const int rg = m0 + rl;
            float2 xv = xpre[half][p];
            __nv_bfloat162 hhi = *(const __nv_bfloat162*)(sAh + rl * SA_PITCH + colg);
            __nv_bfloat162 hlo = *(const __nv_bfloat162*)(sAl + rl * SA_PITCH + colg);
            float hin[2] = {__low2float(hhi) + __low2float(hlo),
                            __high2float(hhi) + __high2float(hlo)};
            float zz[2] = {d[2 * p + 0] + xv.x, d[2 * p + 1] + xv.y};
            float xa[2] = {xv.x, xv.y};
            float hn[2];
            #pragma unroll
            for (int j = 0; j < 2; ++j) {
                float z  = zz[j] + bb2[j];
                float d0 = z - cc[j][0], d1 = z - cc[j][1], d2 = z - cc[j][2];
                float mu0 = __expf(-d0 * d0 * iv[j][0]);
                float mu1 = __expf(-d1 * d1 * iv[j][1]);
                float mu2 = __expf(-d2 * d2 * iv[j][2]);
                float num = mu0 * qq[j][0] + mu1 * qq[j][1] + mu2 * qq[j][2];
                float den = mu0 + mu1 + mu2 + 1e-8f;
                float g   = 1.0f / (1.0f + __expf(-num / den));
                float ex  = __expf(-2.0f * xa[j]);
                float ni  = (1.0f - ex) / (1.0f + ex);
                hn[j] = (1.0f - g) * hin[j] + g * ni;
            }
            __nv_bfloat16 h0i = __float2bfloat16_rn(hn[0]);
            __nv_bfloat16 h1i = __float2bfloat16_rn(hn[1]);
            float l0 = hn[0] - __bfloat162float(h0i);
            float l1 = hn[1] - __bfloat162float(h1i);
            __nv_bfloat162 hiv; hiv.x = h0i; hiv.y = h1i;
            __nv_bfloat162 lov; lov.x = __float2bfloat16_rn(l0);
            lov.y = __float2bfloat16_rn(l1);
            *(__nv_bfloat162*)&hhn[(size_t)rg * HH + colg] = hiv;
            *(__nv_bfloat162*)&hln[(size_t)rg * HH + colg] = lov;
        }
    }

    // ---- PDL trigger AFTER all h stores: pre-trigger writes are visible
    //      to the dependent after its cudaGridDependencySynchronize() ----
    cudaTriggerProgrammaticLaunchCompletion();
}

// ------------------------------------------------------------------
// Final: logits[b] = h_final[b] . Wc + bc
// ------------------------------------------------------------------
__global__ void __launch_bounds__(256) final_kernel(const float* __restrict__ Wc,
                                                    const float* __restrict__ bc,
                                                    float* __restrict__ out)
{
    const int warp = threadIdx.x >> 5;
    const int lane = threadIdx.x & 31;
    const int b = blockIdx.x * 8 + warp;
    const __nv_bfloat16* hhr = g_hh[0] + (size_t)b * HH;
    const __nv_bfloat16* hlr = g_hl[0] + (size_t)b * HH;
    float s = 0.0f;
    #pragma unroll
    for (int i = 0; i < 4; ++i) {
        int h = i * 128 + lane * 4;
        __nv_bfloat162 a0 = *(const __nv_bfloat162*)(hhr + h);
        __nv_bfloat162 a1 = *(const __nv_bfloat162*)(hhr + h + 2);
        __nv_bfloat162 l0 = *(const __nv_bfloat162*)(hlr + h);
        __nv_bfloat162 l1 = *(const __nv_bfloat162*)(hlr + h + 2);
        float4 w4 = *(const float4*)&Wc[h];
        s += (__low2float(a0)  + __low2float(l0))  * w4.x;
        s += (__high2float(a0) + __high2float(l0)) * w4.y;
        s += (__low2float(a1)  + __low2float(l1))  * w4.z;
        s += (__high2float(a1) + __high2float(l1)) * w4.w;
    }
    #pragma unroll
    for (int o = 16; o > 0; o >>= 1) s += __shfl_down_sync(0xffffffffu, s, o);
    if (lane == 0) out[b] = s + bc[0];
}

// ------------------------------------------------------------------
// Launch
// ------------------------------------------------------------------
extern "C" void kernel_launch(void* const* d_in, const int* in_sizes, int n_in,
                              void* d_out, int out_size)
{
    const float* x     = (const float*)d_in[0];
    const float* theta = (const float*)d_in[1];
    const float* Wx    = (const float*)d_in[2];
    const float* Wh    = (const float*)d_in[3];
    const float* bias  = (const float*)d_in[4];
    const float* c     = (const float*)d_in[5];
    const float* sigma = (const float*)d_in[6];
    const float* q     = (const float*)d_in[7];
    const float* Wc    = (const float*)d_in[8];
    const float* bc    = (const float*)d_in[9];
    float* out = (float*)d_out;

    static int configured = 0;
    if (!configured) {
        cudaFuncSetAttribute(step_kernel,
                             cudaFuncAttributeMaxDynamicSharedMemorySize,
                             SMEM_STEP_BYTES);
        cudaFuncSetAttribute(gemm1_hmma,
                             cudaFuncAttributeMaxDynamicSharedMemorySize,
                             SMEM_G1_BYTES);
        configured = 1;
    }

    prep_kernel<<<(BB * HH + 255) / 256, 256>>>(theta, Wx, Wh, sigma, c, q, bias, out);
    xcvt_kernel<<<(BB * TT * FF) / (256 * 4), 256>>>(x);
    gemm1_hmma<<<dim3((BB * TT) / 64, HH / 128), 256, SMEM_G1_BYTES>>>();

    // step kernels with programmatic dependent launch
    cudaLaunchConfig_t cfg = {};
    cfg.gridDim  = dim3(16, 8, 1);
    cfg.blockDim = dim3(256, 1, 1);
    cfg.dynamicSmemBytes = SMEM_STEP_BYTES;
    cudaLaunchAttribute attrs[1];
    attrs[0].id = cudaLaunchAttributeProgrammaticStreamSerialization;
    attrs[0].val.programmaticStreamSerializationAllowed = 1;
    cfg.attrs = attrs;
    cfg.numAttrs = 1;
    for (int t = 0; t < TT; ++t)
        cudaLaunchKernelEx(&cfg, step_kernel, t);

    final_kernel<<<64, 256>>>(Wc, bc, out);
}

// round 17
// speedup vs baseline: 1.1254x; 1.1254x over previous
#include <cuda_runtime.h>
#include <cuda_bf16.h>
#include <math.h>

#define BB   512   // batch
#define TT   128   // time steps
#define FF   256   // features
#define HH   512   // hidden
#define KK   3     // fuzzy rules

typedef unsigned long long ull;
typedef unsigned int uint;

// ------------------------------------------------------------------
// Device scratch
// ------------------------------------------------------------------
__device__ float g_xw[(size_t)TT * BB * HH];          // [T][B][H]
__device__ __nv_bfloat16 g_hh[2][(size_t)BB * HH];    // h hi, ping-pong [B][H]
__device__ __nv_bfloat16 g_hl[2][(size_t)BB * HH];    // h lo
__device__ __nv_bfloat16 g_Whh[HH * HH];              // Wh hi  [k][n]
__device__ __nv_bfloat16 g_Whl[HH * HH];              // Wh lo
__device__ __nv_bfloat16 g_Wxh[FF * HH];              // (sigmoid(theta)*Wx) hi
__device__ __nv_bfloat16 g_Wxl[FF * HH];              // (sigmoid(theta)*Wx) lo
__device__ __nv_bfloat16 g_xh[(size_t)BB * TT * FF];  // x hi  [b*T+t][f]
__device__ __nv_bfloat16 g_xl[(size_t)BB * TT * FF];  // x lo
__device__ float g_gp[(HH / 2) * 20];                 // packed gate params / col-pair

// ------------------------------------------------------------------
// Helpers
// ------------------------------------------------------------------
__device__ __forceinline__ uint smem_u32(const void* p) {
    return (uint)__cvta_generic_to_shared(p);
}
__device__ __forceinline__ void ldmx4(uint* r, uint addr) {
    asm volatile("ldmatrix.sync.aligned.m8n8.x4.shared.b16 {%0,%1,%2,%3}, [%4];"
                 : "=r"(r[0]), "=r"(r[1]), "=r"(r[2]), "=r"(r[3]) : "r"(addr));
}
__device__ __forceinline__ void ldmx4t(uint* r, uint addr) {
    asm volatile("ldmatrix.sync.aligned.m8n8.x4.trans.shared.b16 {%0,%1,%2,%3}, [%4];"
                 : "=r"(r[0]), "=r"(r[1]), "=r"(r[2]), "=r"(r[3]) : "r"(addr));
}
__device__ __forceinline__ void mma16816(float* d, const uint* a, uint b0, uint b1) {
    asm volatile("mma.sync.aligned.m16n8k16.row.col.f32.bf16.bf16.f32 "
                 "{%0,%1,%2,%3}, {%4,%5,%6,%7}, {%8,%9}, {%0,%1,%2,%3};"
                 : "+f"(d[0]), "+f"(d[1]), "+f"(d[2]), "+f"(d[3])
                 : "r"(a[0]), "r"(a[1]), "r"(a[2]), "r"(a[3]), "r"(b0), "r"(b1));
}
__device__ __forceinline__ void cpasync16(uint saddr, const void* gaddr) {
    asm volatile("cp.async.cg.shared.global [%0], [%1], 16;"
                 :: "r"(saddr), "l"(gaddr));
}

// ------------------------------------------------------------------
// Prep: zero h0, split Wh and Wxs into bf16 hi/lo, emit weights, gate params.
// ------------------------------------------------------------------
__global__ void prep_kernel(const float* __restrict__ theta,
                            const float* __restrict__ Wx,
                            const float* __restrict__ Wh,
                            const float* __restrict__ sigma,
                            const float* __restrict__ cC,
                            const float* __restrict__ qQ,
                            const float* __restrict__ bias,
                            float* __restrict__ out)
{
    int idx = blockIdx.x * blockDim.x + threadIdx.x;   // 262144 threads
    if (idx < BB * HH) {
        g_hh[0][idx] = __float2bfloat16_rn(0.0f);
        g_hl[0][idx] = __float2bfloat16_rn(0.0f);
    }
    if (idx < HH * HH) {
        float w = Wh[idx];
        __nv_bfloat16 hi = __float2bfloat16_rn(w);
        g_Whh[idx] = hi;
        g_Whl[idx] = __float2bfloat16_rn(w - __bfloat162float(hi));
    }
    if (idx < FF * HH) {
        int f = idx >> 9;
        float w = (1.0f / (1.0f + expf(-theta[f]))) * Wx[idx];
        __nv_bfloat16 hi = __float2bfloat16_rn(w);
        g_Wxh[idx] = hi;
        g_Wxl[idx] = __float2bfloat16_rn(w - __bfloat162float(hi));
    }
    if (idx < FF) out[BB + idx] = 1.0f / (1.0f + expf(-theta[idx]));
    if (idx < HH / 2) {
        float* gp = g_gp + idx * 20;
        #pragma unroll
        for (int j = 0; j < 2; ++j) {
            int col = idx * 2 + j;
            float* o = gp + j * 10;
            #pragma unroll
            for (int s = 0; s < 3; ++s) {
                float sg = sigma[col * 3 + s];
                o[0 + s] = cC[col * 3 + s];
                o[4 + s] = 1.0f / (2.0f * sg * sg + 1e-8f);
                o[7 + s] = qQ[col * 3 + s];
            }
            o[3] = bias[col];
        }
    }
}

// ------------------------------------------------------------------
// x -> bf16 hi/lo split.
// ------------------------------------------------------------------
__global__ void __launch_bounds__(256) xcvt_kernel(const float* __restrict__ x)
{
    size_t i = ((size_t)blockIdx.x * 256 + threadIdx.x) * 4;
    float4 v = *(const float4*)(x + i);
    __nv_bfloat16 h0 = __float2bfloat16_rn(v.x);
    __nv_bfloat16 h1 = __float2bfloat16_rn(v.y);
    __nv_bfloat16 h2 = __float2bfloat16_rn(v.z);
    __nv_bfloat16 h3 = __float2bfloat16_rn(v.w);
    __nv_bfloat162 hv0; hv0.x = h0; hv0.y = h1;
    __nv_bfloat162 hv1; hv1.x = h2; hv1.y = h3;
    __nv_bfloat162 lv0;
    lv0.x = __float2bfloat16_rn(v.x - __bfloat162float(h0));
    lv0.y = __float2bfloat16_rn(v.y - __bfloat162float(h1));
    __nv_bfloat162 lv1;
    lv1.x = __float2bfloat16_rn(v.z - __bfloat162float(h2));
    lv1.y = __float2bfloat16_rn(v.w - __bfloat162float(h3));
    *(__nv_bfloat162*)(g_xh + i)     = hv0;
    *(__nv_bfloat162*)(g_xh + i + 2) = hv1;
    *(__nv_bfloat162*)(g_xl + i)     = lv0;
    *(__nv_bfloat162*)(g_xl + i + 2) = lv1;
}

// ------------------------------------------------------------------
// GEMM1 v2 (B-resident): g_xw[t][b][h] = sum_f x[m][f] * Wxs[f][h].
// Grid (128, 4): 512 CTAs (3.5 waves). Each CTA stages its Wxs slice
// [256][128] ONCE, then loops 16 m-subtiles (32 rows) with A (x hi/lo)
// double-buffered via cp.async. B traffic cut 8x vs per-tile staging.
// 8 warps = 2m x 4n; warp tile m16 x n32.
// ------------------------------------------------------------------
#define G2_APITCH 264
#define G2_BPITCH 136
#define G2_BH 0
#define G2_BL (FF * G2_BPITCH * 2)                 // 69632
#define G2_A  (2 * FF * G2_BPITCH * 2)             // 139264
#define G2_ALO (32 * G2_APITCH * 2)                // 16896 (lo offset within buf)
#define G2_ABUF (2 * 32 * G2_APITCH * 2)           // 33792 (buffer stride)
#define SMEM_G2_BYTES (G2_A + 2 * G2_ABUF)         // 206848

__global__ void __launch_bounds__(256, 1) gemm1_hmma()
{
    extern __shared__ char smem[];
    const int tid = threadIdx.x;
    const int mg  = blockIdx.x;          // m-group: rows [mg*512, mg*512+512)
    const int n0  = blockIdx.y * 128;

    const uint sB = smem_u32(smem);
    const uint sA = sB + G2_A;

    // ---- stage B (Wxs hi/lo slice, 256 x 128) once ----
    {
        #pragma unroll
        for (int j = 0; j < 16; ++j) {
            int flat = tid + 256 * j;            // < 4096
            int row  = flat >> 4;                // 0..255
            int c8   = flat & 15;
            const size_t src = (size_t)row * HH + n0 + c8 * 8;
            cpasync16(sB + (row * G2_BPITCH + c8 * 8) * 2,         g_Wxh + src);
            cpasync16(sB + G2_BL + (row * G2_BPITCH + c8 * 8) * 2, g_Wxl + src);
        }
    }
    // ---- stage A subtile 0 ----
    {
        #pragma unroll
        for (int j = 0; j < 4; ++j) {
            int flat = tid + 256 * j;            // < 1024
            int row  = flat >> 5;                // 0..31
            int c8   = flat & 31;
            const size_t src = (size_t)(mg * 512 + row) * FF + c8 * 8;
            cpasync16(sA + (row * G2_APITCH + c8 * 8) * 2,          g_xh + src);
            cpasync16(sA + G2_ALO + (row * G2_APITCH + c8 * 8) * 2, g_xl + src);
        }
    }
    asm volatile("cp.async.commit_group;" ::: "memory");
    asm volatile("cp.async.wait_group 0;" ::: "memory");
    __syncthreads();

    const int warp = tid >> 5;
    const int lane = tid & 31;
    const int wm   = warp & 1;           // m16 tile within 32 rows
    const int wn   = warp >> 1;          // n32 tile (0..3)

    // lane addresses (A addr gets buffer offset added per-iteration)
    const uint aOffH = ((wm * 16 + (lane & 15)) * G2_APITCH + (lane >> 4) * 8) * 2;
    uint bAddrH[2], bAddrL[2];
    #pragma unroll
    for (int bsub = 0; bsub < 2; ++bsub) {
        int bRow = lane & 15;
        int bCol = wn * 32 + bsub * 16 + (lane >> 4) * 8;
        bAddrH[bsub] = sB + (bRow * G2_BPITCH + bCol) * 2;
        bAddrL[bsub] = bAddrH[bsub] + G2_BL;
    }

    #pragma unroll 1
    for (int it = 0; it < 16; ++it) {
        const uint bufA = sA + (uint)(it & 1) * G2_ABUF;

        // prefetch next A subtile into the other buffer
        if (it < 15) {
            const uint nbuf = sA + (uint)((it + 1) & 1) * G2_ABUF;
            #pragma unroll
            for (int j = 0; j < 4; ++j) {
                int flat = tid + 256 * j;
                int row  = flat >> 5;
                int c8   = flat & 31;
                const size_t src = (size_t)(mg * 512 + (it + 1) * 32 + row) * FF + c8 * 8;
                cpasync16(nbuf + (row * G2_APITCH + c8 * 8) * 2,          g_xh + src);
                cpasync16(nbuf + G2_ALO + (row * G2_APITCH + c8 * 8) * 2, g_xl + src);
            }
            asm volatile("cp.async.commit_group;" ::: "memory");
        }

        // ---- compute subtile ----
        float acc[4][4];
        #pragma unroll
        for (int j = 0; j < 4; ++j)
            #pragma unroll
            for (int r = 0; r < 4; ++r) acc[j][r] = 0.f;

        const uint aAddrH = bufA + aOffH;
        const uint aAddrL = aAddrH + G2_ALO;

        #pragma unroll 4
        for (int ks = 0; ks < 16; ++ks) {
            uint ah[4], al[4];
            ldmx4(ah, aAddrH + ks * 32);
            ldmx4(al, aAddrL + ks * 32);
            #pragma unroll
            for (int bsub = 0; bsub < 2; ++bsub) {
                uint bh[4], bl[4];
                ldmx4t(bh, bAddrH[bsub] + ks * (16 * G2_BPITCH * 2));
                ldmx4t(bl, bAddrL[bsub] + ks * (16 * G2_BPITCH * 2));
                float* d0 = acc[bsub * 2 + 0];
                float* d1 = acc[bsub * 2 + 1];
                mma16816(d0, ah, bh[0], bh[1]);
                mma16816(d0, ah, bl[0], bl[1]);
                mma16816(d0, al, bh[0], bh[1]);
                mma16816(d1, ah, bh[2], bh[3]);
                mma16816(d1, ah, bl[2], bl[3]);
                mma16816(d1, al, bh[2], bh[3]);
            }
        }

        // ---- epilogue: write fp32 xw in [t][b][h] layout ----
        const int mbase = mg * 512 + it * 32;
        #pragma unroll
        for (int j = 0; j < 4; ++j) {
            const int col = n0 + wn * 32 + j * 8 + (lane & 3) * 2;
            #pragma unroll
            for (int p = 0; p < 2; ++p) {
                int m = mbase + wm * 16 + (lane >> 2) + p * 8;
                int t = m & (TT - 1);
                int b = m >> 7;
                float2 v = make_float2(acc[j][2 * p], acc[j][2 * p + 1]);
                *(float2*)&g_xw[((size_t)t * BB + b) * HH + col] = v;
            }
        }

        if (it < 15) {
            asm volatile("cp.async.wait_group 0;" ::: "memory");
            __syncthreads();
        }
    }
}

// ------------------------------------------------------------------
// Step kernel (R14, proven best): PDL, cp.async staging, xw prefetch,
// trigger after mainloop (safe: cudaGridDependencySynchronize waits for
// full predecessor completion; trigger only gates early launch).
// ------------------------------------------------------------------
#define SA_PITCH 520
#define SB_PITCH 72
#define SMEM_AH  0
#define SMEM_AL  (32 * SA_PITCH * 2)
#define SMEM_BH  (2 * 32 * SA_PITCH * 2)
#define SMEM_BL  (SMEM_BH + HH * SB_PITCH * 2)
#define SMEM_STEP_BYTES (SMEM_BL + HH * SB_PITCH * 2)

__global__ void __launch_bounds__(256, 1) step_kernel(int t)
{
    extern __shared__ char smem[];
    __nv_bfloat16* sAh = (__nv_bfloat16*)(smem + SMEM_AH);
    __nv_bfloat16* sAl = (__nv_bfloat16*)(smem + SMEM_AL);

    const int tid = threadIdx.x;
    const int m0  = blockIdx.x * 32;
    const int n0  = blockIdx.y * 64;

    const uint sAhU = smem_u32(smem + SMEM_AH);
    const uint sAlU = smem_u32(smem + SMEM_AL);
    const uint sBhU = smem_u32(smem + SMEM_BH);
    const uint sBlU = smem_u32(smem + SMEM_BL);

    // ---- stage B (Wh hi/lo slice) — independent of predecessor ----
    {
        #pragma unroll
        for (int j = 0; j < 16; ++j) {
            int flat = tid + 256 * j;          // < 4096
            int row  = flat >> 3;              // 0..511
            int c8   = flat & 7;
            const size_t src = (size_t)row * HH + n0 + c8 * 8;
            cpasync16(sBhU + (row * SB_PITCH + c8 * 8) * 2, g_Whh + src);
            cpasync16(sBlU + (row * SB_PITCH + c8 * 8) * 2, g_Whl + src);
        }
    }
    asm volatile("cp.async.commit_group;" ::: "memory");

    const int warp = tid >> 5;
    const int lane = tid & 31;
    const int mw   = warp & 1;
    const int nw   = warp >> 1;
    const int rl0  = mw * 16 + (lane >> 2);
    const int c0   = (lane & 3) * 2;

    // ---- gate params (prep output, 2+ kernels back — safe pre-sync) ----
    float4 gpre[2][5];
    #pragma unroll
    for (int half = 0; half < 2; ++half) {
        const int colg = n0 + nw * 16 + half * 8 + c0;
        const float* gp = g_gp + (size_t)(colg >> 1) * 20;
        gpre[half][0] = *(const float4*)(gp + 0);
        gpre[half][1] = *(const float4*)(gp + 4);
        gpre[half][2] = *(const float4*)(gp + 8);
        gpre[half][3] = *(const float4*)(gp + 12);
        gpre[half][4] = *(const float4*)(gp + 16);
    }

    // ---- wait for predecessor's h / xw writes ----
    cudaGridDependencySynchronize();

    const __nv_bfloat16* hh = g_hh[t & 1];
    const __nv_bfloat16* hl = g_hl[t & 1];

    // ---- stage A (h hi/lo) via cp.async ----
    {
        #pragma unroll
        for (int j = 0; j < 8; ++j) {
            int flat = tid + 256 * j;          // < 2048
            int row  = flat >> 6;              // 0..31
            int c8   = flat & 63;
            const size_t src = (size_t)(m0 + row) * HH + c8 * 8;
            cpasync16(sAhU + (row * SA_PITCH + c8 * 8) * 2, hh + src);
            cpasync16(sAlU + (row * SA_PITCH + c8 * 8) * 2, hl + src);
        }
    }
    asm volatile("cp.async.commit_group;" ::: "memory");

    // ---- xw prefetch (DRAM-cold) overlaps the A staging wait ----
    const float* xwt = g_xw + (size_t)t * (BB * HH);
    float2 xpre[2][2];
    #pragma unroll
    for (int half = 0; half < 2; ++half) {
        const int colg = n0 + nw * 16 + half * 8 + c0;
        #pragma unroll
        for (int p = 0; p < 2; ++p) {
            const int rg = m0 + rl0 + p * 8;
            xpre[half][p] = *(const float2*)&xwt[(size_t)rg * HH + colg];
        }
    }

    asm volatile("cp.async.wait_group 0;" ::: "memory");
    __syncthreads();

    // ---- HMMA mainloop ----
    const int aRow = mw * 16 + (lane & 15);
    const int aCol = (lane >> 4) * 8;
    uint aAddrH = sAhU + (aRow * SA_PITCH + aCol) * 2;
    uint aAddrL = aAddrH + (SMEM_AL - SMEM_AH);

    const int bRow = lane & 15;
    const int bCol = nw * 16 + (lane >> 4) * 8;
    uint bAddrH = sBhU + (bRow * SB_PITCH + bCol) * 2;
    uint bAddrL = bAddrH + (SMEM_BL - SMEM_BH);

    float acc0[4] = {0.f, 0.f, 0.f, 0.f};
    float acc1[4] = {0.f, 0.f, 0.f, 0.f};

    #pragma unroll 4
    for (int ks = 0; ks < 32; ++ks) {
        uint ah[4], al[4], bh[4], bl[4];
        ldmx4 (ah, aAddrH + ks * 32);
        ldmx4 (al, aAddrL + ks * 32);
        ldmx4t(bh, bAddrH + ks * (16 * SB_PITCH * 2));
        ldmx4t(bl, bAddrL + ks * (16 * SB_PITCH * 2));
        mma16816(acc0, ah, bh[0], bh[1]);
        mma16816(acc0, ah, bl[0], bl[1]);
        mma16816(acc0, al, bh[0], bh[1]);
        mma16816(acc1, ah, bh[2], bh[3]);
        mma16816(acc1, ah, bl[2], bl[3]);
        mma16816(acc1, al, bh[2], bh[3]);
    }

    // ---- let the next step launch & stage its B while we finish ----
    cudaTriggerProgrammaticLaunchCompletion();

    // ---- fused gate epilogue ----
    __nv_bfloat16* hhn = g_hh[(t + 1) & 1];
    __nv_bfloat16* hln = g_hl[(t + 1) & 1];

    float* accs[2] = {acc0, acc1};
    #pragma unroll
    for (int half = 0; half < 2; ++half) {
        const float* d = accs[half];
        const int colg = n0 + nw * 16 + half * 8 + c0;

        float4 p0 = gpre[half][0];
        float4 p1 = gpre[half][1];
        float4 p2 = gpre[half][2];
        float4 p3 = gpre[half][3];
        float4 p4 = gpre[half][4];
        float cc[2][3]  = {{p0.x, p0.y, p0.z}, {p2.z, p2.w, p3.x}};
        float bb2[2]    = {p0.w, p3.y};
        float iv[2][3]  = {{p1.x, p1.y, p1.z}, {p3.z, p3.w, p4.x}};
        float qq[2][3]  = {{p1.w, p2.x, p2.y}, {p4.y, p4.z, p4.w}};

        #pragma unroll
        for (int p = 0; p < 2; ++p) {
            const int rl = rl0 + p * 8;
            const int rg = m0 + rl;
            float2 xv = xpre[half][p];
            __nv_bfloat162 hhi = *(const __nv_bfloat162*)(sAh + rl * SA_PITCH + colg);
            __nv_bfloat162 hlo = *(const __nv_bfloat162*)(sAl + rl * SA_PITCH + colg);
            float hin[2] = {__low2float(hhi) + __low2float(hlo),
                            __high2float(hhi) + __high2float(hlo)};
            float zz[2] = {d[2 * p + 0] + xv.x, d[2 * p + 1] + xv.y};
            float xa[2] = {xv.x, xv.y};
            float hn[2];
            #pragma unroll
            for (int j = 0; j < 2; ++j) {
                float z  = zz[j] + bb2[j];
                float d0 = z - cc[j][0], d1 = z - cc[j][1], d2 = z - cc[j][2];
                float mu0 = __expf(-d0 * d0 * iv[j][0]);
                float mu1 = __expf(-d1 * d1 * iv[j][1]);
                float mu2 = __expf(-d2 * d2 * iv[j][2]);
                float num = mu0 * qq[j][0] + mu1 * qq[j][1] + mu2 * qq[j][2];
                float den = mu0 + mu1 + mu2 + 1e-8f;
                float g   = 1.0f / (1.0f + __expf(-num / den));
                float ex  = __expf(-2.0f * xa[j]);
                float ni  = (1.0f - ex) / (1.0f + ex);
                hn[j] = (1.0f - g) * hin[j] + g * ni;
            }
            __nv_bfloat16 h0i = __float2bfloat16_rn(hn[0]);
            __nv_bfloat16 h1i = __float2bfloat16_rn(hn[1]);
            float l0 = hn[0] - __bfloat162float(h0i);
            float l1 = hn[1] - __bfloat162float(h1i);
            __nv_bfloat162 hiv; hiv.x = h0i; hiv.y = h1i;
            __nv_bfloat162 lov; lov.x = __float2bfloat16_rn(l0);
            lov.y = __float2bfloat16_rn(l1);
            *(__nv_bfloat162*)&hhn[(size_t)rg * HH + colg] = hiv;
            *(__nv_bfloat162*)&hln[(size_t)rg * HH + colg] = lov;
        }
    }
}

// ------------------------------------------------------------------
// Final: logits[b] = h_final[b] . Wc + bc
// ------------------------------------------------------------------
__global__ void __launch_bounds__(256) final_kernel(const float* __restrict__ Wc,
                                                    const float* __restrict__ bc,
                                                    float* __restrict__ out)
{
    const int warp = threadIdx.x >> 5;
    const int lane = threadIdx.x & 31;
    const int b = blockIdx.x * 8 + warp;
    const __nv_bfloat16* hhr = g_hh[0] + (size_t)b * HH;
    const __nv_bfloat16* hlr = g_hl[0] + (size_t)b * HH;
    float s = 0.0f;
    #pragma unroll
    for (int i = 0; i < 4; ++i) {
        int h = i * 128 + lane * 4;
        __nv_bfloat162 a0 = *(const __nv_bfloat162*)(hhr + h);
        __nv_bfloat162 a1 = *(const __nv_bfloat162*)(hhr + h + 2);
        __nv_bfloat162 l0 = *(const __nv_bfloat162*)(hlr + h);
        __nv_bfloat162 l1 = *(const __nv_bfloat162*)(hlr + h + 2);
        float4 w4 = *(const float4*)&Wc[h];
        s += (__low2float(a0)  + __low2float(l0))  * w4.x;
        s += (__high2float(a0) + __high2float(l0)) * w4.y;
        s += (__low2float(a1)  + __low2float(l1))  * w4.z;
        s += (__high2float(a1) + __high2float(l1)) * w4.w;
    }
    #pragma unroll
    for (int o = 16; o > 0; o >>= 1) s += __shfl_down_sync(0xffffffffu, s, o);
    if (lane == 0) out[b] = s + bc[0];
}

// ------------------------------------------------------------------
// Launch
// ------------------------------------------------------------------
extern "C" void kernel_launch(void* const* d_in, const int* in_sizes, int n_in,
                              void* d_out, int out_size)
{
    const float* x     = (const float*)d_in[0];
    const float* theta = (const float*)d_in[1];
    const float* Wx    = (const float*)d_in[2];
    const float* Wh    = (const float*)d_in[3];
    const float* bias  = (const float*)d_in[4];
    const float* c     = (const float*)d_in[5];
    const float* sigma = (const float*)d_in[6];
    const float* q     = (const float*)d_in[7];
    const float* Wc    = (const float*)d_in[8];
    const float* bc    = (const float*)d_in[9];
    float* out = (float*)d_out;

    static int configured = 0;
    if (!configured) {
        cudaFuncSetAttribute(step_kernel,
                             cudaFuncAttributeMaxDynamicSharedMemorySize,
                             SMEM_STEP_BYTES);
        cudaFuncSetAttribute(gemm1_hmma,
                             cudaFuncAttributeMaxDynamicSharedMemorySize,
                             SMEM_G2_BYTES);
        configured = 1;
    }

    prep_kernel<<<(BB * HH + 255) / 256, 256>>>(theta, Wx, Wh, sigma, c, q, bias, out);
    xcvt_kernel<<<(BB * TT * FF) / (256 * 4), 256>>>(x);
    gemm1_hmma<<<dim3(128, 4), 256, SMEM_G2_BYTES>>>();

    // step kernels with programmatic dependent launch
    cudaLaunchConfig_t cfg = {};
    cfg.gridDim  = dim3(16, 8, 1);
    cfg.blockDim = dim3(256, 1, 1);
    cfg.dynamicSmemBytes = SMEM_STEP_BYTES;
    cudaLaunchAttribute attrs[1];
    attrs[0].id = cudaLaunchAttributeProgrammaticStreamSerialization;
    attrs[0].val.programmaticStreamSerializationAllowed = 1;
    cfg.attrs = attrs;
    cfg.numAttrs = 1;
    for (int t = 0; t < TT; ++t)
        cudaLaunchKernelEx(&cfg, step_kernel, t);

    final_kernel<<<64, 256>>>(Wc, bc, out);
}